// round 2
// baseline (speedup 1.0000x reference)
#include <cuda_runtime.h>

// u, z: (B=4, C=2048, H=64, W=64) fp32, C = N_T(8) * N_CAPS(16) * CAP_DIM(16)
// v[b,t,c,d,hw] = sum_{kt,kd} w[kt][kd] * u^2[b,(t+kt-1)%8, c, (d+kd-1)%16, hw]
// out = (z + beta) * rsqrt(v + 1e-6)

#define NT   8
#define NC   16
#define CD   16
#define CCH  (NT*NC*CD)   // 2048
#define HWT  32           // hw tile per block
#define NTHREADS 512

__global__ __launch_bounds__(NTHREADS, 3)
void caps_fused_kernel(const float* __restrict__ z,
                       const float* __restrict__ u,
                       const float* __restrict__ wgt,
                       const float* __restrict__ beta_p,
                       float* __restrict__ out,
                       int hw_total)               // 4096
{
    __shared__ float usq[NT * CD * HWT];          // 16 KB

    const int ntile     = hw_total / HWT;         // 128
    const int tilesPerB = NC * ntile;             // 2048

    const int bid  = blockIdx.x;
    const int b    = bid / tilesPerB;
    const int rem  = bid % tilesPerB;
    const int c    = rem / ntile;
    const int tile = rem % ntile;
    const int hw0  = tile * HWT;

    const int tid  = threadIdx.x;
    const int baseB = b * CCH * hw_total;
    const int cOff  = c * CD;

    // ---------------- Phase 1: load u tile, square into smem (float4) -------
    // 8*16 rows * 32 hw = 4096 floats = 1024 float4 -> 2 per thread.
    #pragma unroll
    for (int i = 0; i < 2; ++i) {
        int e4  = tid + i * NTHREADS;             // 0..1023
        int chl = e4 >> 3;                        // 8 float4 per 32-float row
        int hw4 = e4 & 7;
        int t   = chl >> 4;
        int d   = chl & 15;
        int gch = t * (NC * CD) + cOff + d;
        const float4 v4 = *reinterpret_cast<const float4*>(
            u + baseB + gch * hw_total + hw0 + hw4 * 4);
        float4 s4;
        s4.x = v4.x * v4.x; s4.y = v4.y * v4.y;
        s4.z = v4.z * v4.z; s4.w = v4.w * v4.w;
        *reinterpret_cast<float4*>(&usq[chl * HWT + hw4 * 4]) = s4;
    }
    __syncthreads();

    // ---------------- Phase 2: stencil + normalize (all float4) -------------
    const float beta = beta_p[0];

    const int hw4 = (tid & 7) * 4;                // hw offset within tile
    const int d2  = (tid >> 3) & 7;               // which d-pair
    const int t   = tid >> 6;                     // 0..7
    const int d0  = d2 * 2;
    const int d1  = d0 + 1;
    const int tm  = (t + NT - 1) & (NT - 1);
    const int tp  = (t + 1) & (NT - 1);
    const int dm  = (d0 + CD - 1) & (CD - 1);
    const int dp  = (d1 + 1) & (CD - 1);

    float4 v0 = make_float4(0.f, 0.f, 0.f, 0.f);
    float4 v1 = make_float4(0.f, 0.f, 0.f, 0.f);

    const int rows[3] = { tm, t, tp };
    #pragma unroll
    for (int r = 0; r < 3; ++r) {
        const float* base = &usq[rows[r] * CD * HWT + hw4];
        const float4 xa = *reinterpret_cast<const float4*>(base + dm * HWT);
        const float4 xb = *reinterpret_cast<const float4*>(base + d0 * HWT);
        const float4 xc = *reinterpret_cast<const float4*>(base + d1 * HWT);
        const float4 xd = *reinterpret_cast<const float4*>(base + dp * HWT);
        const float wr0 = wgt[r * 3 + 0];
        const float wr1 = wgt[r * 3 + 1];
        const float wr2 = wgt[r * 3 + 2];
        v0.x = fmaf(wr0, xa.x, fmaf(wr1, xb.x, fmaf(wr2, xc.x, v0.x)));
        v0.y = fmaf(wr0, xa.y, fmaf(wr1, xb.y, fmaf(wr2, xc.y, v0.y)));
        v0.z = fmaf(wr0, xa.z, fmaf(wr1, xb.z, fmaf(wr2, xc.z, v0.z)));
        v0.w = fmaf(wr0, xa.w, fmaf(wr1, xb.w, fmaf(wr2, xc.w, v0.w)));
        v1.x = fmaf(wr0, xb.x, fmaf(wr1, xc.x, fmaf(wr2, xd.x, v1.x)));
        v1.y = fmaf(wr0, xb.y, fmaf(wr1, xc.y, fmaf(wr2, xd.y, v1.y)));
        v1.z = fmaf(wr0, xb.z, fmaf(wr1, xc.z, fmaf(wr2, xd.z, v1.z)));
        v1.w = fmaf(wr0, xb.w, fmaf(wr1, xc.w, fmaf(wr2, xd.w, v1.w)));
    }

    const int gch0 = t * (NC * CD) + cOff + d0;
    const long off0 = (long)baseB + (long)gch0 * hw_total + hw0 + hw4;

    const float4 z0 = *reinterpret_cast<const float4*>(z + off0);
    const float4 z1 = *reinterpret_cast<const float4*>(z + off0 + hw_total);

    float4 o0, o1;
    o0.x = (z0.x + beta) * __frsqrt_rn(v0.x + 1e-6f);
    o0.y = (z0.y + beta) * __frsqrt_rn(v0.y + 1e-6f);
    o0.z = (z0.z + beta) * __frsqrt_rn(v0.z + 1e-6f);
    o0.w = (z0.w + beta) * __frsqrt_rn(v0.w + 1e-6f);
    o1.x = (z1.x + beta) * __frsqrt_rn(v1.x + 1e-6f);
    o1.y = (z1.y + beta) * __frsqrt_rn(v1.y + 1e-6f);
    o1.z = (z1.z + beta) * __frsqrt_rn(v1.z + 1e-6f);
    o1.w = (z1.w + beta) * __frsqrt_rn(v1.w + 1e-6f);

    *reinterpret_cast<float4*>(out + off0)            = o0;
    *reinterpret_cast<float4*>(out + off0 + hw_total) = o1;
}

extern "C" void kernel_launch(void* const* d_in, const int* in_sizes, int n_in,
                              void* d_out, int out_size)
{
    const float* z    = (const float*)d_in[0];
    const float* u    = (const float*)d_in[1];
    const float* wgt  = (const float*)d_in[2];   // 9 floats
    const float* beta = (const float*)d_in[3];   // 1 float
    float* out        = (float*)d_out;

    const int hw_total = 64 * 64;                          // 4096
    const int B        = in_sizes[0] / (CCH * hw_total);   // 4
    const int grid     = B * NC * (hw_total / HWT);        // 8192 blocks

    caps_fused_kernel<<<grid, NTHREADS>>>(z, u, wgt, beta, out, hw_total);
}

// round 3
// speedup vs baseline: 1.0394x; 1.0394x over previous
#include <cuda_runtime.h>

// u, z: (B=4, C=2048, H=64, W=64) fp32, C = N_T(8) * N_CAPS(16) * CAP_DIM(16)
// v[b,t,c,d,hw] = sum_{kt,kd} w[kt][kd] * u^2[b,(t+kt-1)%8, c, (d+kd-1)%16, hw]
// out = (z + beta) * rsqrt(v + 1e-6)

#define NT   8
#define NC   16
#define CD   16
#define CCH  (NT*NC*CD)   // 2048
#define HWT  32           // hw tile per block
#define NTHREADS 256

__constant__ float c_w[9];
__constant__ float c_beta[1];

__global__ __launch_bounds__(NTHREADS, 4)
void caps_fused_kernel(const float* __restrict__ z,
                       const float* __restrict__ u,
                       float* __restrict__ out)
{
    __shared__ float usq[NT * CD * HWT];          // 16 KB

    const int hw_total = 4096;

    const int bid  = blockIdx.x;
    const int b    = bid >> 11;                   // / 2048
    const int rem  = bid & 2047;
    const int c    = rem >> 7;                    // / 128
    const int tile = rem & 127;
    const int hw0  = tile * HWT;

    const int tid   = threadIdx.x;
    const int baseB = b * CCH * hw_total;
    const int cOff  = c * CD;

    // Output mapping: 4 float4 outputs per thread.
    const int hw4 = (tid & 7) * 4;                // hw offset within tile
    const int d2  = (tid >> 3) & 3;               // d-pair selector
    const int t   = tid >> 5;                     // 0..7
    const int da  = d2 * 2;                       // first d-pair base  (0,2,4,6)
    const int db  = da + 8;                       // second d-pair base (8,10,12,14)
    const int tm  = (t + NT - 1) & (NT - 1);
    const int tp  = (t + 1) & (NT - 1);

    // ---------------- Phase 1a: load u tile, square into smem ---------------
    // 8*16 rows * 32 hw = 4096 floats = 1024 float4 -> 4 per thread.
    #pragma unroll
    for (int i = 0; i < 4; ++i) {
        int e4  = tid + i * NTHREADS;             // 0..1023
        int chl = e4 >> 3;                        // 8 float4 per 32-float row
        int h4  = (e4 & 7) * 4;
        int tt  = chl >> 4;
        int dd  = chl & 15;
        int gch = tt * (NC * CD) + cOff + dd;
        const float4 v4 = *reinterpret_cast<const float4*>(
            u + baseB + gch * hw_total + hw0 + h4);
        float4 s4;
        s4.x = v4.x * v4.x; s4.y = v4.y * v4.y;
        s4.z = v4.z * v4.z; s4.w = v4.w * v4.w;
        *reinterpret_cast<float4*>(&usq[chl * HWT + h4]) = s4;
    }

    // ---------------- Phase 1b: prefetch z (overlaps with barrier wait) -----
    const int   gchBase = t * (NC * CD) + cOff;
    const float* zp = z + baseB + gchBase * hw_total + hw0 + hw4;
    const float4 z0 = *reinterpret_cast<const float4*>(zp + (da    ) * hw_total);
    const float4 z1 = *reinterpret_cast<const float4*>(zp + (da + 1) * hw_total);
    const float4 z2 = *reinterpret_cast<const float4*>(zp + (db    ) * hw_total);
    const float4 z3 = *reinterpret_cast<const float4*>(zp + (db + 1) * hw_total);

    __syncthreads();

    // ---------------- Phase 2: stencil + normalize (smem + regs only) -------
    const float beta = c_beta[0];
    float* op = out + baseB + gchBase * hw_total + hw0 + hw4;

    #pragma unroll
    for (int g = 0; g < 2; ++g) {
        const int d0 = (g == 0) ? da : db;
        const int d1 = d0 + 1;
        const int dm = (d0 + CD - 1) & (CD - 1);
        const int dp = (d0 + 2) & (CD - 1);

        float4 v0 = make_float4(0.f, 0.f, 0.f, 0.f);
        float4 v1 = make_float4(0.f, 0.f, 0.f, 0.f);

        const int rows[3] = { tm, t, tp };
        #pragma unroll
        for (int r = 0; r < 3; ++r) {
            const float* bp = &usq[rows[r] * CD * HWT + hw4];
            const float4 xa = *reinterpret_cast<const float4*>(bp + dm * HWT);
            const float4 xb = *reinterpret_cast<const float4*>(bp + d0 * HWT);
            const float4 xc = *reinterpret_cast<const float4*>(bp + d1 * HWT);
            const float4 xd = *reinterpret_cast<const float4*>(bp + dp * HWT);
            const float w0 = c_w[r * 3 + 0];
            const float w1 = c_w[r * 3 + 1];
            const float w2 = c_w[r * 3 + 2];
            v0.x = fmaf(w0, xa.x, fmaf(w1, xb.x, fmaf(w2, xc.x, v0.x)));
            v0.y = fmaf(w0, xa.y, fmaf(w1, xb.y, fmaf(w2, xc.y, v0.y)));
            v0.z = fmaf(w0, xa.z, fmaf(w1, xb.z, fmaf(w2, xc.z, v0.z)));
            v0.w = fmaf(w0, xa.w, fmaf(w1, xb.w, fmaf(w2, xc.w, v0.w)));
            v1.x = fmaf(w0, xb.x, fmaf(w1, xc.x, fmaf(w2, xd.x, v1.x)));
            v1.y = fmaf(w0, xb.y, fmaf(w1, xc.y, fmaf(w2, xd.y, v1.y)));
            v1.z = fmaf(w0, xb.z, fmaf(w1, xc.z, fmaf(w2, xd.z, v1.z)));
            v1.w = fmaf(w0, xb.w, fmaf(w1, xc.w, fmaf(w2, xd.w, v1.w)));
        }

        const float4 zz0 = (g == 0) ? z0 : z2;
        const float4 zz1 = (g == 0) ? z1 : z3;

        float4 o0, o1;
        o0.x = (zz0.x + beta) * __frsqrt_rn(v0.x + 1e-6f);
        o0.y = (zz0.y + beta) * __frsqrt_rn(v0.y + 1e-6f);
        o0.z = (zz0.z + beta) * __frsqrt_rn(v0.z + 1e-6f);
        o0.w = (zz0.w + beta) * __frsqrt_rn(v0.w + 1e-6f);
        o1.x = (zz1.x + beta) * __frsqrt_rn(v1.x + 1e-6f);
        o1.y = (zz1.y + beta) * __frsqrt_rn(v1.y + 1e-6f);
        o1.z = (zz1.z + beta) * __frsqrt_rn(v1.z + 1e-6f);
        o1.w = (zz1.w + beta) * __frsqrt_rn(v1.w + 1e-6f);

        *reinterpret_cast<float4*>(op + d0 * hw_total) = o0;
        *reinterpret_cast<float4*>(op + d1 * hw_total) = o1;
    }
}

extern "C" void kernel_launch(void* const* d_in, const int* in_sizes, int n_in,
                              void* d_out, int out_size)
{
    const float* z   = (const float*)d_in[0];
    const float* u   = (const float*)d_in[1];
    float* out       = (float*)d_out;

    // Weights (9 floats) + beta (1 float) -> constant memory (D2D, graph-legal).
    cudaMemcpyToSymbolAsync(c_w,    d_in[2], 9 * sizeof(float), 0,
                            cudaMemcpyDeviceToDevice);
    cudaMemcpyToSymbolAsync(c_beta, d_in[3], 1 * sizeof(float), 0,
                            cudaMemcpyDeviceToDevice);

    const int hw_total = 64 * 64;                          // 4096
    const int B        = in_sizes[0] / (CCH * hw_total);   // 4
    const int grid     = B * NC * (hw_total / HWT);        // 8192 blocks

    caps_fused_kernel<<<grid, NTHREADS>>>(z, u, out);
}

// round 4
// speedup vs baseline: 1.2226x; 1.1763x over previous
#include <cuda_runtime.h>

// u, z: (B=4, C=2048, H=64, W=64) fp32, C = N_T(8) * N_CAPS(16) * CAP_DIM(16)
// v[b,t,c,d,hw] = sum_{kt,kd} w[kt][kd] * u^2[b,(t+kt-1)%8, c, (d+kd-1)%16, hw]
// out = (z + beta) * rsqrt(v + 1e-6)

#define NT   8
#define NC   16
#define CD   16
#define CCH  (NT*NC*CD)     // 2048
#define HWTOT 4096
#define TSTRIDE (NC*CD*HWTOT)   // 256*4096 elements between consecutive t

__constant__ float c_w[9];
__constant__ float c_beta[1];

// No shared memory, no barriers. lanes -> hw, warp -> d, thread computes all 8 t.
__global__ __launch_bounds__(256, 3)
void caps_nosmem_kernel(const float* __restrict__ z,
                        const float* __restrict__ u,
                        float* __restrict__ out)
{
    const int tid  = threadIdx.x;
    const int lane = tid & 31;
    const int warp = tid >> 5;                 // 0..7

    const int bid  = blockIdx.x;
    const int b    = bid >> 12;                // 4096 blocks per batch
    const int rem  = bid & 4095;
    const int c    = rem >> 8;                 // 256 blocks per capsule
    const int rem2 = rem & 255;
    const int dg   = rem2 >> 7;                // d-half: 0 or 1
    const int tile = rem2 & 127;               // hw tile
    const int hw0  = tile * 32;

    const int d  = dg * 8 + warp;              // 0..15
    const int dm = (d + CD - 1) & (CD - 1);
    const int dp = (d + 1) & (CD - 1);

    const int baseB = b * (CCH * HWTOT);
    const int cOff  = c * CD;
    const int hwoff = hw0 + lane;

    const float* ub = u + baseB + hwoff;
    const float* zb = z + baseB + hwoff;

    const int chm = (cOff + dm) * HWTOT;
    const int ch0 = (cOff + d ) * HWTOT;
    const int chp = (cOff + dp) * HWTOT;

    // ---- load burst: 24 u loads + 8 z loads, all independent ----
    float am[NT], a0[NT], ap[NT], zv[NT];
    #pragma unroll
    for (int t = 0; t < NT; ++t) {
        const int toff = t * TSTRIDE;
        am[t] = ub[toff + chm];
        a0[t] = ub[toff + ch0];
        ap[t] = ub[toff + chp];
    }
    #pragma unroll
    for (int t = 0; t < NT; ++t)
        zv[t] = zb[t * TSTRIDE + ch0];

    const float w00 = c_w[0], w01 = c_w[1], w02 = c_w[2];
    const float w10 = c_w[3], w11 = c_w[4], w12 = c_w[5];
    const float w20 = c_w[6], w21 = c_w[7], w22 = c_w[8];
    const float beta = c_beta[0];

    float v[NT];
    #pragma unroll
    for (int t = 0; t < NT; ++t) v[t] = 0.f;

    // Each source row t' scatters into outputs t'-1, t', t'+1 (wrap).
    // a[t'][kt] uses weight row kt; v[t] = sum_kt a[t+kt-1][kt].
    #pragma unroll
    for (int tp_ = 0; tp_ < NT; ++tp_) {
        const float sm = am[tp_] * am[tp_];
        const float s0 = a0[tp_] * a0[tp_];
        const float sp = ap[tp_] * ap[tp_];
        const int tn = (tp_ + 1) & (NT - 1);       // receives weight row 0
        const int tb = (tp_ + NT - 1) & (NT - 1);  // receives weight row 2
        v[tn]  = fmaf(w00, sm, fmaf(w01, s0, fmaf(w02, sp, v[tn])));
        v[tp_] = fmaf(w10, sm, fmaf(w11, s0, fmaf(w12, sp, v[tp_])));
        v[tb]  = fmaf(w20, sm, fmaf(w21, s0, fmaf(w22, sp, v[tb])));
    }

    float* ob = out + baseB + hwoff;
    #pragma unroll
    for (int t = 0; t < NT; ++t)
        ob[t * TSTRIDE + ch0] = (zv[t] + beta) * __frsqrt_rn(v[t] + 1e-6f);
}

extern "C" void kernel_launch(void* const* d_in, const int* in_sizes, int n_in,
                              void* d_out, int out_size)
{
    const float* z   = (const float*)d_in[0];
    const float* u   = (const float*)d_in[1];
    float* out       = (float*)d_out;

    cudaMemcpyToSymbolAsync(c_w,    d_in[2], 9 * sizeof(float), 0,
                            cudaMemcpyDeviceToDevice);
    cudaMemcpyToSymbolAsync(c_beta, d_in[3], 1 * sizeof(float), 0,
                            cudaMemcpyDeviceToDevice);

    const int B    = in_sizes[0] / (CCH * HWTOT);     // 4
    const int grid = B * NC * 2 * 128;                // 16384 blocks

    caps_nosmem_kernel<<<grid, 256>>>(z, u, out);
}

// round 6
// speedup vs baseline: 1.4026x; 1.1473x over previous
#include <cuda_runtime.h>

// u, z: (B=4, C=2048, H=64, W=64) fp32, C = N_T(8) * N_CAPS(16) * CAP_DIM(16)
// v[b,t,c,d,hw] = sum_{kt,kd} w[kt][kd] * u^2[b,(t+kt-1)%8, c, (d+kd-1)%16, hw]
// out = (z + beta) * rsqrt(v + 1e-6)

#define NT   8
#define NC   16
#define CD   16
#define CCH  (NT*NC*CD)        // 2048
#define HWTOT 4096
#define TSTRIDE (NC*CD*HWTOT)  // elements between consecutive t

typedef unsigned long long u64;

__constant__ float c_w[9];
__constant__ float c_beta[1];

__device__ __forceinline__ u64 fma2(u64 a, u64 b, u64 c) {
    u64 d; asm("fma.rn.f32x2 %0, %1, %2, %3;" : "=l"(d) : "l"(a), "l"(b), "l"(c));
    return d;
}
__device__ __forceinline__ u64 mul2(u64 a, u64 b) {
    u64 d; asm("mul.rn.f32x2 %0, %1, %2;" : "=l"(d) : "l"(a), "l"(b));
    return d;
}
__device__ __forceinline__ u64 add2(u64 a, u64 b) {
    u64 d; asm("add.rn.f32x2 %0, %1, %2;" : "=l"(d) : "l"(a), "l"(b));
    return d;
}
__device__ __forceinline__ u64 pack2(float lo, float hi) {
    u64 r; asm("mov.b64 %0, {%1, %2};" : "=l"(r) : "f"(lo), "f"(hi));
    return r;
}
__device__ __forceinline__ void unpack2(u64 v, float& lo, float& hi) {
    asm("mov.b64 {%0, %1}, %2;" : "=f"(lo), "=f"(hi) : "l"(v));
}

// No smem, no barriers. lane -> 2 hw, warp -> d, thread computes all 8 t.
__global__ __launch_bounds__(256, 2)
void caps_f32x2_kernel(const float* __restrict__ z,
                       const float* __restrict__ u,
                       float* __restrict__ out)
{
    const int tid  = threadIdx.x;
    const int lane = tid & 31;
    const int warp = tid >> 5;                 // 0..7

    const int bid  = blockIdx.x;               // 8192 total
    const int b    = bid >> 11;                // 2048 blocks per batch
    const int rem  = bid & 2047;
    const int c    = rem >> 7;                 // 128 blocks per capsule
    const int rem2 = rem & 127;
    const int dg   = rem2 >> 6;                // d-half: 0 or 1
    const int tile = rem2 & 63;                // hw tile (64 hw each)
    const int hw0  = tile * 64;

    const int d  = dg * 8 + warp;              // 0..15
    const int dm = (d + CD - 1) & (CD - 1);
    const int dp = (d + 1) & (CD - 1);

    const int baseB = b * (CCH * HWTOT);
    const int cOff  = c * CD;
    const int hwoff = hw0 + lane * 2;

    const float* ub = u + baseB + hwoff;
    const float* zb = z + baseB + hwoff;

    const int chm = (cOff + dm) * HWTOT;
    const int ch0 = (cOff + d ) * HWTOT;
    const int chp = (cOff + dp) * HWTOT;

    // ---- load burst: 24 u + 8 z LDG.64, all independent ----
    u64 am[NT], a0[NT], ap[NT], zv[NT];
    #pragma unroll
    for (int t = 0; t < NT; ++t) {
        const int toff = t * TSTRIDE;
        am[t] = *reinterpret_cast<const u64*>(ub + toff + chm);
        a0[t] = *reinterpret_cast<const u64*>(ub + toff + ch0);
        ap[t] = *reinterpret_cast<const u64*>(ub + toff + chp);
    }
    #pragma unroll
    for (int t = 0; t < NT; ++t)
        zv[t] = *reinterpret_cast<const u64*>(zb + t * TSTRIDE + ch0);

    const u64 w00 = pack2(c_w[0], c_w[0]), w01 = pack2(c_w[1], c_w[1]), w02 = pack2(c_w[2], c_w[2]);
    const u64 w10 = pack2(c_w[3], c_w[3]), w11 = pack2(c_w[4], c_w[4]), w12 = pack2(c_w[5], c_w[5]);
    const u64 w20 = pack2(c_w[6], c_w[6]), w21 = pack2(c_w[7], c_w[7]), w22 = pack2(c_w[8], c_w[8]);
    const u64 betap = pack2(c_beta[0], c_beta[0]);
    const u64 epsp  = pack2(1e-6f, 1e-6f);

    u64 v[NT];
    #pragma unroll
    for (int t = 0; t < NT; ++t) v[t] = 0ull;

    // Source row t' scatters into outputs t'+1 (w row 0), t' (row 1), t'-1 (row 2).
    #pragma unroll
    for (int s = 0; s < NT; ++s) {
        const u64 sm = mul2(am[s], am[s]);
        const u64 s0 = mul2(a0[s], a0[s]);
        const u64 sp = mul2(ap[s], ap[s]);
        const int tn = (s + 1) & (NT - 1);
        const int tb = (s + NT - 1) & (NT - 1);
        v[tn] = fma2(w00, sm, fma2(w01, s0, fma2(w02, sp, v[tn])));
        v[s]  = fma2(w10, sm, fma2(w11, s0, fma2(w12, sp, v[s])));
        v[tb] = fma2(w20, sm, fma2(w21, s0, fma2(w22, sp, v[tb])));
    }

    float* ob = out + baseB + hwoff;
    #pragma unroll
    for (int t = 0; t < NT; ++t) {
        const u64 vz = add2(zv[t], betap);
        const u64 vv = add2(v[t], epsp);
        float vlo, vhi;
        unpack2(vv, vlo, vhi);
        const u64 r = pack2(__frsqrt_rn(vlo), __frsqrt_rn(vhi));
        const u64 o = mul2(vz, r);
        *reinterpret_cast<u64*>(ob + t * TSTRIDE + ch0) = o;
    }
}

extern "C" void kernel_launch(void* const* d_in, const int* in_sizes, int n_in,
                              void* d_out, int out_size)
{
    const float* z   = (const float*)d_in[0];
    const float* u   = (const float*)d_in[1];
    float* out       = (float*)d_out;

    cudaMemcpyToSymbolAsync(c_w,    d_in[2], 9 * sizeof(float), 0,
                            cudaMemcpyDeviceToDevice);
    cudaMemcpyToSymbolAsync(c_beta, d_in[3], 1 * sizeof(float), 0,
                            cudaMemcpyDeviceToDevice);

    const int B    = in_sizes[0] / (CCH * HWTOT);     // 4
    const int grid = B * NC * 2 * 64;                 // 8192 blocks

    caps_f32x2_kernel<<<grid, 256>>>(z, u, out);
}